// round 1
// baseline (speedup 1.0000x reference)
#include <cuda_runtime.h>
#include <math.h>

// ---------------- problem constants ----------------
#define T_TOK 4096
#define HIDN  2048
#define NH    16
#define NKV   4
#define HD    128
#define FF    8192
#define BATCH 4
#define SEQ   1024
#define GRP   (NH / NKV)          // 4
#define KVW   (NKV * HD)          // 512
#define EPSV  1e-6f
#define SCALE 0.08838834764831845f  // 1/sqrt(128)

// ---------------- scratch (single device global, ~688MB) ----------------
// h:      4096*2048  =  8388608
// q:      4096*2048  =  8388608
// k:      4096*512   =  2097152
// v:      4096*512   =  2097152
// scores: 64*1024*1024 = 67108864
// attn:   4096*2048  =  8388608
// x2:     4096*2048  =  8388608
// gate:   4096*8192  = 33554432
// up:     4096*8192  = 33554432
#define OFF_H      ((size_t)0)
#define OFF_Q      ((size_t)8388608)
#define OFF_K      ((size_t)16777216)
#define OFF_V      ((size_t)18874368)
#define OFF_SCORES ((size_t)20971520)
#define OFF_ATTN   ((size_t)88080384)
#define OFF_X2     ((size_t)96468992)
#define OFF_GATE   ((size_t)104857600)
#define OFF_UP     ((size_t)138412032)
#define SCRATCH_FLOATS ((size_t)171966464)

__device__ float g_scratch[SCRATCH_FLOATS];

// ---------------- GEMM tile config ----------------
#define BM 128
#define BN 128
#define BKK 8
#define TM 8
#define TN 8

// C[M,N] = A[M,K] @ B[N,K]^T  (+ bias / + residual), row-major, strided.
// EPI: 0 = none, 1 = +bias[n], 2 = +res[m*ldc+n]
template <int EPI>
__global__ void __launch_bounds__(256)
gemm_tn_kernel(const float* __restrict__ A, int lda,
               const float* __restrict__ B, int ldb,
               float* __restrict__ C, int ldc,
               int K,
               const float* __restrict__ bias,
               const float* __restrict__ res)
{
    __shared__ float As[BKK][BM];
    __shared__ float Bs[BKK][BN];
    const int tid = threadIdx.x;
    const int m0 = blockIdx.y * BM;
    const int n0 = blockIdx.x * BN;
    const int tx = tid & 15;
    const int ty = tid >> 4;
    const int lr = tid >> 1;          // 0..127
    const int lc = (tid & 1) << 2;    // 0 or 4

    const float* Ap = A + (size_t)(m0 + lr) * lda + lc;
    const float* Bp = B + (size_t)(n0 + lr) * ldb + lc;

    float acc[TM][TN];
#pragma unroll
    for (int i = 0; i < TM; i++)
#pragma unroll
        for (int j = 0; j < TN; j++) acc[i][j] = 0.f;

    for (int k0 = 0; k0 < K; k0 += BKK) {
        float4 av = *(const float4*)(Ap + k0);
        float4 bv = *(const float4*)(Bp + k0);
        As[lc + 0][lr] = av.x; As[lc + 1][lr] = av.y;
        As[lc + 2][lr] = av.z; As[lc + 3][lr] = av.w;
        Bs[lc + 0][lr] = bv.x; Bs[lc + 1][lr] = bv.y;
        Bs[lc + 2][lr] = bv.z; Bs[lc + 3][lr] = bv.w;
        __syncthreads();
#pragma unroll
        for (int kk = 0; kk < BKK; kk++) {
            float af[TM], bf[TN];
#pragma unroll
            for (int i = 0; i < TM; i++) af[i] = As[kk][ty * TM + i];
#pragma unroll
            for (int j = 0; j < TN; j++) bf[j] = Bs[kk][tx * TN + j];
#pragma unroll
            for (int i = 0; i < TM; i++)
#pragma unroll
                for (int j = 0; j < TN; j++) acc[i][j] += af[i] * bf[j];
        }
        __syncthreads();
    }

#pragma unroll
    for (int i = 0; i < TM; i++) {
        size_t row = (size_t)(m0 + ty * TM + i);
#pragma unroll
        for (int j = 0; j < TN; j++) {
            size_t col = (size_t)(n0 + tx * TN + j);
            float vv = acc[i][j];
            if (EPI == 1) vv += bias[col];
            if (EPI == 2) vv += res[row * (size_t)ldc + col];
            C[row * (size_t)ldc + col] = vv;
        }
    }
}

// scores[z, s, t] = (q[b,s,h,:] . k[b,t,kvh,:]) * SCALE + mask[b,s,t]
__global__ void __launch_bounds__(256)
attn_scores_kernel(const float* __restrict__ q, const float* __restrict__ k,
                   const float* __restrict__ mask, float* __restrict__ scores)
{
    const int z = blockIdx.z;
    const int b = z / NH, h = z % NH, kvh = h / GRP;
    const float* A = q + (size_t)b * SEQ * HIDN + (size_t)h * HD;   // lda=HIDN
    const float* B = k + (size_t)b * SEQ * KVW + (size_t)kvh * HD;  // ldb=KVW
    float* C = scores + (size_t)z * SEQ * SEQ;
    const float* M = mask + (size_t)b * SEQ * SEQ;

    __shared__ float As[BKK][BM];
    __shared__ float Bs[BKK][BN];
    const int tid = threadIdx.x;
    const int m0 = blockIdx.y * BM;
    const int n0 = blockIdx.x * BN;
    const int tx = tid & 15;
    const int ty = tid >> 4;
    const int lr = tid >> 1;
    const int lc = (tid & 1) << 2;

    const float* Ap = A + (size_t)(m0 + lr) * HIDN + lc;
    const float* Bp = B + (size_t)(n0 + lr) * KVW + lc;

    float acc[TM][TN];
#pragma unroll
    for (int i = 0; i < TM; i++)
#pragma unroll
        for (int j = 0; j < TN; j++) acc[i][j] = 0.f;

    for (int k0 = 0; k0 < HD; k0 += BKK) {
        float4 av = *(const float4*)(Ap + k0);
        float4 bv = *(const float4*)(Bp + k0);
        As[lc + 0][lr] = av.x; As[lc + 1][lr] = av.y;
        As[lc + 2][lr] = av.z; As[lc + 3][lr] = av.w;
        Bs[lc + 0][lr] = bv.x; Bs[lc + 1][lr] = bv.y;
        Bs[lc + 2][lr] = bv.z; Bs[lc + 3][lr] = bv.w;
        __syncthreads();
#pragma unroll
        for (int kk = 0; kk < BKK; kk++) {
            float af[TM], bf[TN];
#pragma unroll
            for (int i = 0; i < TM; i++) af[i] = As[kk][ty * TM + i];
#pragma unroll
            for (int j = 0; j < TN; j++) bf[j] = Bs[kk][tx * TN + j];
#pragma unroll
            for (int i = 0; i < TM; i++)
#pragma unroll
                for (int j = 0; j < TN; j++) acc[i][j] += af[i] * bf[j];
        }
        __syncthreads();
    }

#pragma unroll
    for (int i = 0; i < TM; i++) {
        size_t row = (size_t)(m0 + ty * TM + i);
#pragma unroll
        for (int j = 0; j < TN; j++) {
            size_t col = (size_t)(n0 + tx * TN + j);
            C[row * SEQ + col] = acc[i][j] * SCALE + M[row * SEQ + col];
        }
    }
}

// attn[b,s,h,:] = sum_t p[z,s,t] * v[b,t,kvh,:]   (NN-form GEMM, N=HD=128)
__global__ void __launch_bounds__(256)
attn_pv_kernel(const float* __restrict__ p, const float* __restrict__ v,
               float* __restrict__ out)
{
    const int z = blockIdx.z;
    const int b = z / NH, h = z % NH, kvh = h / GRP;
    const float* A = p + (size_t)z * SEQ * SEQ;                      // lda=SEQ
    const float* B = v + (size_t)b * SEQ * KVW + (size_t)kvh * HD;   // ldb=KVW, K x N
    float* C = out + (size_t)b * SEQ * HIDN + (size_t)h * HD;        // ldc=HIDN

    __shared__ float As[BKK][BM];
    __shared__ float Bs[BKK][BN];
    const int tid = threadIdx.x;
    const int m0 = blockIdx.y * BM;
    const int tx = tid & 15;
    const int ty = tid >> 4;
    const int lr = tid >> 1;
    const int lc = (tid & 1) << 2;
    const int br = tid >> 5;           // 0..7
    const int bc = (tid & 31) << 2;    // 0..124

    const float* Ap = A + (size_t)(m0 + lr) * SEQ + lc;

    float acc[TM][TN];
#pragma unroll
    for (int i = 0; i < TM; i++)
#pragma unroll
        for (int j = 0; j < TN; j++) acc[i][j] = 0.f;

    for (int k0 = 0; k0 < SEQ; k0 += BKK) {
        float4 av = *(const float4*)(Ap + k0);
        float4 bv = *(const float4*)(B + (size_t)(k0 + br) * KVW + bc);
        As[lc + 0][lr] = av.x; As[lc + 1][lr] = av.y;
        As[lc + 2][lr] = av.z; As[lc + 3][lr] = av.w;
        Bs[br][bc + 0] = bv.x; Bs[br][bc + 1] = bv.y;
        Bs[br][bc + 2] = bv.z; Bs[br][bc + 3] = bv.w;
        __syncthreads();
#pragma unroll
        for (int kk = 0; kk < BKK; kk++) {
            float af[TM], bf[TN];
#pragma unroll
            for (int i = 0; i < TM; i++) af[i] = As[kk][ty * TM + i];
#pragma unroll
            for (int j = 0; j < TN; j++) bf[j] = Bs[kk][tx * TN + j];
#pragma unroll
            for (int i = 0; i < TM; i++)
#pragma unroll
                for (int j = 0; j < TN; j++) acc[i][j] += af[i] * bf[j];
        }
        __syncthreads();
    }

#pragma unroll
    for (int i = 0; i < TM; i++) {
        size_t row = (size_t)(m0 + ty * TM + i);
#pragma unroll
        for (int j = 0; j < TN; j++) {
            size_t col = (size_t)(tx * TN + j);
            C[row * HIDN + col] = acc[i][j];
        }
    }
}

// row-wise softmax over length SEQ=1024 (256 threads, 4 elems/thread)
__global__ void __launch_bounds__(256)
softmax_kernel(float* __restrict__ s)
{
    const size_t base = (size_t)blockIdx.x * SEQ;
    const int tid = threadIdx.x;
    __shared__ float red[8];

    float vals[4];
    float mx = -1e30f;
#pragma unroll
    for (int j = 0; j < 4; j++) {
        vals[j] = s[base + tid + j * 256];
        mx = fmaxf(mx, vals[j]);
    }
#pragma unroll
    for (int o = 16; o > 0; o >>= 1) mx = fmaxf(mx, __shfl_xor_sync(0xffffffffu, mx, o));
    if ((tid & 31) == 0) red[tid >> 5] = mx;
    __syncthreads();
    float m2 = fmaxf(fmaxf(fmaxf(red[0], red[1]), fmaxf(red[2], red[3])),
                     fmaxf(fmaxf(red[4], red[5]), fmaxf(red[6], red[7])));
    __syncthreads();

    float sum = 0.f;
#pragma unroll
    for (int j = 0; j < 4; j++) {
        vals[j] = expf(vals[j] - m2);
        sum += vals[j];
    }
#pragma unroll
    for (int o = 16; o > 0; o >>= 1) sum += __shfl_xor_sync(0xffffffffu, sum, o);
    if ((tid & 31) == 0) red[tid >> 5] = sum;
    __syncthreads();
    float tot = red[0] + red[1] + red[2] + red[3] + red[4] + red[5] + red[6] + red[7];
    float inv = 1.f / tot;
#pragma unroll
    for (int j = 0; j < 4; j++) s[base + tid + j * 256] = vals[j] * inv;
}

// RMSNorm over HIDN=2048, one block per row
__global__ void __launch_bounds__(256)
rmsnorm_kernel(const float* __restrict__ x, const float* __restrict__ w,
               float* __restrict__ out)
{
    const size_t base = (size_t)blockIdx.x * HIDN;
    const int tid = threadIdx.x;
    __shared__ float red[8];

    float v[8];
    float ss = 0.f;
#pragma unroll
    for (int j = 0; j < 8; j++) {
        v[j] = x[base + tid + j * 256];
        ss += v[j] * v[j];
    }
#pragma unroll
    for (int o = 16; o > 0; o >>= 1) ss += __shfl_xor_sync(0xffffffffu, ss, o);
    if ((tid & 31) == 0) red[tid >> 5] = ss;
    __syncthreads();
    float tot = red[0] + red[1] + red[2] + red[3] + red[4] + red[5] + red[6] + red[7];
    float r = rsqrtf(tot * (1.f / HIDN) + EPSV);
#pragma unroll
    for (int j = 0; j < 8; j++)
        out[base + tid + j * 256] = v[j] * r * w[tid + j * 256];
}

// per-(token,head) RMSNorm over HD=128 + RoPE, in place. blockDim=128.
__global__ void __launch_bounds__(128)
head_rms_rope_kernel(float* __restrict__ buf, const float* __restrict__ w,
                     const float* __restrict__ cs, const float* __restrict__ sn,
                     int nheads)
{
    const int t = blockIdx.x;
    const int h = blockIdx.y;
    const int i = threadIdx.x;  // 0..127
    const size_t idx = (size_t)t * nheads * HD + (size_t)h * HD + i;

    float v = buf[idx];
    float ss = v * v;
#pragma unroll
    for (int o = 16; o > 0; o >>= 1) ss += __shfl_xor_sync(0xffffffffu, ss, o);
    __shared__ float red[4];
    if ((i & 31) == 0) red[i >> 5] = ss;
    __syncthreads();
    float tot = red[0] + red[1] + red[2] + red[3];
    float n = v * rsqrtf(tot * (1.f / HD) + EPSV) * w[i];

    __shared__ float sm[HD];
    sm[i] = n;
    __syncthreads();
    float rot = (i < 64) ? -sm[i + 64] : sm[i - 64];
    buf[idx] = n * cs[(size_t)t * HD + i] + rot * sn[(size_t)t * HD + i];
}

// g[i] = silu(g[i]) * u[i]
__global__ void __launch_bounds__(256)
silu_mul_kernel(float* __restrict__ g, const float* __restrict__ u, size_t n)
{
    size_t i = (size_t)blockIdx.x * blockDim.x + threadIdx.x;
    size_t stride = (size_t)gridDim.x * blockDim.x;
    for (; i < n; i += stride) {
        float gv = g[i];
        g[i] = gv / (1.f + expf(-gv)) * u[i];
    }
}

extern "C" void kernel_launch(void* const* d_in, const int* in_sizes, int n_in,
                              void* d_out, int out_size)
{
    const float* x    = (const float*)d_in[0];
    const float* cosv = (const float*)d_in[1];
    const float* sinv = (const float*)d_in[2];
    const float* mask = (const float*)d_in[3];
    const float* wq   = (const float*)d_in[4];
    const float* bq   = (const float*)d_in[5];
    const float* wk   = (const float*)d_in[6];
    const float* bk   = (const float*)d_in[7];
    const float* wv   = (const float*)d_in[8];
    const float* bv   = (const float*)d_in[9];
    const float* wo   = (const float*)d_in[10];
    const float* qw   = (const float*)d_in[11];
    const float* kw   = (const float*)d_in[12];
    const float* ln1  = (const float*)d_in[13];
    const float* ln2  = (const float*)d_in[14];
    const float* wg   = (const float*)d_in[15];
    const float* wu   = (const float*)d_in[16];
    const float* wd   = (const float*)d_in[17];
    float* out = (float*)d_out;

    float* s = nullptr;
    cudaGetSymbolAddress((void**)&s, g_scratch);
    float* h      = s + OFF_H;
    float* q      = s + OFF_Q;
    float* kbuf   = s + OFF_K;
    float* vbuf   = s + OFF_V;
    float* scores = s + OFF_SCORES;
    float* attn   = s + OFF_ATTN;
    float* x2     = s + OFF_X2;
    float* gate   = s + OFF_GATE;
    float* up     = s + OFF_UP;

    // 1. h = rmsnorm(x, ln1)
    rmsnorm_kernel<<<T_TOK, 256>>>(x, ln1, h);

    // 2-4. QKV projections (+bias)
    gemm_tn_kernel<1><<<dim3(HIDN / BN, T_TOK / BM), 256>>>(h, HIDN, wq, HIDN, q, HIDN, HIDN, bq, nullptr);
    gemm_tn_kernel<1><<<dim3(KVW  / BN, T_TOK / BM), 256>>>(h, HIDN, wk, HIDN, kbuf, KVW, HIDN, bk, nullptr);
    gemm_tn_kernel<1><<<dim3(KVW  / BN, T_TOK / BM), 256>>>(h, HIDN, wv, HIDN, vbuf, KVW, HIDN, bv, nullptr);

    // 5-6. per-head RMS + RoPE (in place)
    head_rms_rope_kernel<<<dim3(T_TOK, NH),  HD>>>(q,    qw, cosv, sinv, NH);
    head_rms_rope_kernel<<<dim3(T_TOK, NKV), HD>>>(kbuf, kw, cosv, sinv, NKV);

    // 7. scores = QK^T * scale + mask
    attn_scores_kernel<<<dim3(SEQ / BN, SEQ / BM, BATCH * NH), 256>>>(q, kbuf, mask, scores);

    // 8. softmax over keys
    softmax_kernel<<<BATCH * NH * SEQ, 256>>>(scores);

    // 9. attn = P @ V
    attn_pv_kernel<<<dim3(1, SEQ / BM, BATCH * NH), 256>>>(scores, vbuf, attn);

    // 10. x2 = x + attn @ wo^T
    gemm_tn_kernel<2><<<dim3(HIDN / BN, T_TOK / BM), 256>>>(attn, HIDN, wo, HIDN, x2, HIDN, HIDN, nullptr, x);

    // 11. h = rmsnorm(x2, ln2)
    rmsnorm_kernel<<<T_TOK, 256>>>(x2, ln2, h);

    // 12-13. gate / up projections
    gemm_tn_kernel<0><<<dim3(FF / BN, T_TOK / BM), 256>>>(h, HIDN, wg, HIDN, gate, FF, HIDN, nullptr, nullptr);
    gemm_tn_kernel<0><<<dim3(FF / BN, T_TOK / BM), 256>>>(h, HIDN, wu, HIDN, up, FF, HIDN, nullptr, nullptr);

    // 14. gate = silu(gate) * up
    silu_mul_kernel<<<8192, 256>>>(gate, up, (size_t)T_TOK * FF);

    // 15. out = x2 + gate @ wd^T
    gemm_tn_kernel<2><<<dim3(HIDN / BN, T_TOK / BM), 256>>>(gate, FF, wd, FF, out, HIDN, FF, nullptr, x2);
}

// round 2
// speedup vs baseline: 1.8532x; 1.8532x over previous
#include <cuda_runtime.h>
#include <mma.h>
#include <math.h>

using namespace nvcuda;

// ---------------- problem constants ----------------
#define T_TOK 4096
#define HIDN  2048
#define NH    16
#define NKV   4
#define HD    128
#define FF    8192
#define BATCH 4
#define SEQ   1024
#define GRP   (NH / NKV)          // 4
#define KVW   (NKV * HD)          // 512
#define EPSV  1e-6f
#define SCALE 0.08838834764831845f  // 1/sqrt(128)
#define NEGV  -1000000000.0f

// ---------------- scratch ----------------
#define OFF_H      ((size_t)0)
#define OFF_Q      ((size_t)8388608)
#define OFF_K      ((size_t)16777216)
#define OFF_V      ((size_t)18874368)
#define OFF_SCORES ((size_t)20971520)
#define OFF_ATTN   ((size_t)88080384)
#define OFF_X2     ((size_t)96468992)
#define OFF_GATE   ((size_t)104857600)
#define OFF_UP     ((size_t)138412032)
#define SCRATCH_FLOATS ((size_t)171966464)

__device__ float g_scratch[SCRATCH_FLOATS];

// ---------------- wmma tf32 GEMM config ----------------
// Block tile 128x128, BK=16. 256 threads = 8 warps, warp tile 64x32.
// wmma shape m16n16k8 (tf32). Accum fp32.
#define BM 128
#define BN 128
#define BKT 16
#define APITCH 20   // 16 + 4 pad
#define BPITCH 20
#define BPITCH_NN 132  // for [BK][BN] layout (PV)

__device__ __forceinline__ float tf32r(float x) { return wmma::__float_to_tf32(x); }

// ============================================================
// TN GEMM: C[M,N] = A[M,K] @ B[N,K]^T  (+epilogue)
// EPI: 0 none, 1 +bias[n], 2 +res[m*ldc+n]
// ============================================================
template <int EPI>
__global__ void __launch_bounds__(256)
wgemm_tn(const float* __restrict__ A, int lda,
         const float* __restrict__ B, int ldb,
         float* __restrict__ C, int ldc, int K,
         const float* __restrict__ bias,
         const float* __restrict__ res)
{
    __shared__ __align__(16) float smem[10240];   // 40KB
    float* sA[2] = { smem,        smem + 2560 };
    float* sB[2] = { smem + 5120, smem + 7680 };

    const int tid  = threadIdx.x;
    const int wid  = tid >> 5;
    const int lane = tid & 31;
    const int m0 = blockIdx.y * BM;
    const int n0 = blockIdx.x * BN;
    const int wm = wid & 1;      // 0..1 -> 64-row slab
    const int wn = wid >> 1;     // 0..3 -> 32-col slab

    wmma::fragment<wmma::accumulator, 16, 16, 8, float> c[4][2];
#pragma unroll
    for (int i = 0; i < 4; i++)
#pragma unroll
        for (int j = 0; j < 2; j++) wmma::fill_fragment(c[i][j], 0.f);

    const int lr  = tid >> 2;        // 0..63
    const int lc4 = (tid & 3) << 2;  // 0,4,8,12

    const float* Abase = A + (size_t)(m0 + lr) * lda + lc4;
    const float* Bbase = B + (size_t)(n0 + lr) * ldb + lc4;

    float4 ra0, ra1, rb0, rb1;

    // prologue: tile 0
    ra0 = *(const float4*)(Abase);
    ra1 = *(const float4*)(Abase + (size_t)64 * lda);
    rb0 = *(const float4*)(Bbase);
    rb1 = *(const float4*)(Bbase + (size_t)64 * ldb);
    {
        float* a = sA[0] + lr * APITCH + lc4;
        a[0] = tf32r(ra0.x); a[1] = tf32r(ra0.y); a[2] = tf32r(ra0.z); a[3] = tf32r(ra0.w);
        float* a2 = sA[0] + (lr + 64) * APITCH + lc4;
        a2[0] = tf32r(ra1.x); a2[1] = tf32r(ra1.y); a2[2] = tf32r(ra1.z); a2[3] = tf32r(ra1.w);
        float* b = sB[0] + lr * BPITCH + lc4;
        b[0] = tf32r(rb0.x); b[1] = tf32r(rb0.y); b[2] = tf32r(rb0.z); b[3] = tf32r(rb0.w);
        float* b2 = sB[0] + (lr + 64) * BPITCH + lc4;
        b2[0] = tf32r(rb1.x); b2[1] = tf32r(rb1.y); b2[2] = tf32r(rb1.z); b2[3] = tf32r(rb1.w);
    }
    __syncthreads();

    const int ntiles = K / BKT;
    for (int t = 0; t < ntiles; t++) {
        const int cur = t & 1;
        if (t + 1 < ntiles) {
            const int k0 = (t + 1) * BKT;
            ra0 = *(const float4*)(Abase + k0);
            ra1 = *(const float4*)(Abase + (size_t)64 * lda + k0);
            rb0 = *(const float4*)(Bbase + k0);
            rb1 = *(const float4*)(Bbase + (size_t)64 * ldb + k0);
        }
#pragma unroll
        for (int ks = 0; ks < BKT; ks += 8) {
            wmma::fragment<wmma::matrix_a, 16, 16, 8, wmma::precision::tf32, wmma::row_major> af[4];
            wmma::fragment<wmma::matrix_b, 16, 16, 8, wmma::precision::tf32, wmma::col_major> bf[2];
#pragma unroll
            for (int i = 0; i < 4; i++)
                wmma::load_matrix_sync(af[i], sA[cur] + (wm * 64 + i * 16) * APITCH + ks, APITCH);
#pragma unroll
            for (int j = 0; j < 2; j++)
                wmma::load_matrix_sync(bf[j], sB[cur] + (wn * 32 + j * 16) * BPITCH + ks, BPITCH);
#pragma unroll
            for (int i = 0; i < 4; i++)
#pragma unroll
                for (int j = 0; j < 2; j++)
                    wmma::mma_sync(c[i][j], af[i], bf[j], c[i][j]);
        }
        if (t + 1 < ntiles) {
            const int nxt = cur ^ 1;
            float* a = sA[nxt] + lr * APITCH + lc4;
            a[0] = tf32r(ra0.x); a[1] = tf32r(ra0.y); a[2] = tf32r(ra0.z); a[3] = tf32r(ra0.w);
            float* a2 = sA[nxt] + (lr + 64) * APITCH + lc4;
            a2[0] = tf32r(ra1.x); a2[1] = tf32r(ra1.y); a2[2] = tf32r(ra1.z); a2[3] = tf32r(ra1.w);
            float* b = sB[nxt] + lr * BPITCH + lc4;
            b[0] = tf32r(rb0.x); b[1] = tf32r(rb0.y); b[2] = tf32r(rb0.z); b[3] = tf32r(rb0.w);
            float* b2 = sB[nxt] + (lr + 64) * BPITCH + lc4;
            b2[0] = tf32r(rb1.x); b2[1] = tf32r(rb1.y); b2[2] = tf32r(rb1.z); b2[3] = tf32r(rb1.w);
        }
        __syncthreads();
    }

    // epilogue: stage per-warp 16x16, apply EPI, vector store
    float* stage = smem + wid * 256;
    const int r  = lane >> 1;
    const int cq = (lane & 1) << 3;
#pragma unroll
    for (int i = 0; i < 4; i++) {
#pragma unroll
        for (int j = 0; j < 2; j++) {
            wmma::store_matrix_sync(stage, c[i][j], 16, wmma::mem_row_major);
            __syncwarp();
            const size_t row_g = (size_t)(m0 + wm * 64 + i * 16 + r);
            const size_t col_g = (size_t)(n0 + wn * 32 + j * 16 + cq);
            float4 v0 = *(float4*)&stage[r * 16 + cq];
            float4 v1 = *(float4*)&stage[r * 16 + cq + 4];
            if (EPI == 1) {
                float4 b0 = *(const float4*)&bias[col_g];
                float4 b1 = *(const float4*)&bias[col_g + 4];
                v0.x += b0.x; v0.y += b0.y; v0.z += b0.z; v0.w += b0.w;
                v1.x += b1.x; v1.y += b1.y; v1.z += b1.z; v1.w += b1.w;
            }
            if (EPI == 2) {
                float4 r0 = *(const float4*)&res[row_g * ldc + col_g];
                float4 r1 = *(const float4*)&res[row_g * ldc + col_g + 4];
                v0.x += r0.x; v0.y += r0.y; v0.z += r0.z; v0.w += r0.w;
                v1.x += r1.x; v1.y += r1.y; v1.z += r1.z; v1.w += r1.w;
            }
            *(float4*)&C[row_g * ldc + col_g] = v0;
            *(float4*)&C[row_g * ldc + col_g + 4] = v1;
            __syncwarp();
        }
    }
}

// ============================================================
// Attention scores: scores[z,s,t] = (q . k)*SCALE + mask
// TN core, K = HD = 128. Fully-masked blocks short-circuit.
// ============================================================
__global__ void __launch_bounds__(256)
wattn_scores(const float* __restrict__ q, const float* __restrict__ k,
             const float* __restrict__ mask, float* __restrict__ scores)
{
    const int z = blockIdx.z;
    const int b = z / NH, h = z % NH, kvh = h / GRP;
    const int m0 = blockIdx.y * BM;
    const int n0 = blockIdx.x * BN;
    float* C = scores + (size_t)z * SEQ * SEQ;

    // fully masked block (strictly above diagonal)
    if (blockIdx.x > blockIdx.y) {
        for (int e = threadIdx.x; e < BM * BN / 4; e += 256) {
            int row = e / (BN / 4);
            int col = (e % (BN / 4)) * 4;
            float4 v = make_float4(NEGV, NEGV, NEGV, NEGV);
            *(float4*)&C[(size_t)(m0 + row) * SEQ + n0 + col] = v;
        }
        return;
    }

    const float* A = q + (size_t)b * SEQ * HIDN + (size_t)h * HD;
    const float* B = k + (size_t)b * SEQ * KVW + (size_t)kvh * HD;
    const float* M = mask + (size_t)b * SEQ * SEQ;

    __shared__ __align__(16) float smem[10240];
    float* sA[2] = { smem,        smem + 2560 };
    float* sB[2] = { smem + 5120, smem + 7680 };

    const int tid  = threadIdx.x;
    const int wid  = tid >> 5;
    const int lane = tid & 31;
    const int wm = wid & 1, wn = wid >> 1;

    wmma::fragment<wmma::accumulator, 16, 16, 8, float> c[4][2];
#pragma unroll
    for (int i = 0; i < 4; i++)
#pragma unroll
        for (int j = 0; j < 2; j++) wmma::fill_fragment(c[i][j], 0.f);

    const int lr  = tid >> 2;
    const int lc4 = (tid & 3) << 2;
    const float* Abase = A + (size_t)(m0 + lr) * HIDN + lc4;
    const float* Bbase = B + (size_t)(n0 + lr) * KVW + lc4;

    float4 ra0, ra1, rb0, rb1;
    ra0 = *(const float4*)(Abase);
    ra1 = *(const float4*)(Abase + (size_t)64 * HIDN);
    rb0 = *(const float4*)(Bbase);
    rb1 = *(const float4*)(Bbase + (size_t)64 * KVW);
    {
        float* a = sA[0] + lr * APITCH + lc4;
        a[0] = tf32r(ra0.x); a[1] = tf32r(ra0.y); a[2] = tf32r(ra0.z); a[3] = tf32r(ra0.w);
        float* a2 = sA[0] + (lr + 64) * APITCH + lc4;
        a2[0] = tf32r(ra1.x); a2[1] = tf32r(ra1.y); a2[2] = tf32r(ra1.z); a2[3] = tf32r(ra1.w);
        float* bp = sB[0] + lr * BPITCH + lc4;
        bp[0] = tf32r(rb0.x); bp[1] = tf32r(rb0.y); bp[2] = tf32r(rb0.z); bp[3] = tf32r(rb0.w);
        float* b2 = sB[0] + (lr + 64) * BPITCH + lc4;
        b2[0] = tf32r(rb1.x); b2[1] = tf32r(rb1.y); b2[2] = tf32r(rb1.z); b2[3] = tf32r(rb1.w);
    }
    __syncthreads();

    const int ntiles = HD / BKT;  // 8
    for (int t = 0; t < ntiles; t++) {
        const int cur = t & 1;
        if (t + 1 < ntiles) {
            const int k0 = (t + 1) * BKT;
            ra0 = *(const float4*)(Abase + k0);
            ra1 = *(const float4*)(Abase + (size_t)64 * HIDN + k0);
            rb0 = *(const float4*)(Bbase + k0);
            rb1 = *(const float4*)(Bbase + (size_t)64 * KVW + k0);
        }
#pragma unroll
        for (int ks = 0; ks < BKT; ks += 8) {
            wmma::fragment<wmma::matrix_a, 16, 16, 8, wmma::precision::tf32, wmma::row_major> af[4];
            wmma::fragment<wmma::matrix_b, 16, 16, 8, wmma::precision::tf32, wmma::col_major> bf[2];
#pragma unroll
            for (int i = 0; i < 4; i++)
                wmma::load_matrix_sync(af[i], sA[cur] + (wm * 64 + i * 16) * APITCH + ks, APITCH);
#pragma unroll
            for (int j = 0; j < 2; j++)
                wmma::load_matrix_sync(bf[j], sB[cur] + (wn * 32 + j * 16) * BPITCH + ks, BPITCH);
#pragma unroll
            for (int i = 0; i < 4; i++)
#pragma unroll
                for (int j = 0; j < 2; j++)
                    wmma::mma_sync(c[i][j], af[i], bf[j], c[i][j]);
        }
        if (t + 1 < ntiles) {
            const int nxt = cur ^ 1;
            float* a = sA[nxt] + lr * APITCH + lc4;
            a[0] = tf32r(ra0.x); a[1] = tf32r(ra0.y); a[2] = tf32r(ra0.z); a[3] = tf32r(ra0.w);
            float* a2 = sA[nxt] + (lr + 64) * APITCH + lc4;
            a2[0] = tf32r(ra1.x); a2[1] = tf32r(ra1.y); a2[2] = tf32r(ra1.z); a2[3] = tf32r(ra1.w);
            float* bp = sB[nxt] + lr * BPITCH + lc4;
            bp[0] = tf32r(rb0.x); bp[1] = tf32r(rb0.y); bp[2] = tf32r(rb0.z); bp[3] = tf32r(rb0.w);
            float* b2 = sB[nxt] + (lr + 64) * BPITCH + lc4;
            b2[0] = tf32r(rb1.x); b2[1] = tf32r(rb1.y); b2[2] = tf32r(rb1.z); b2[3] = tf32r(rb1.w);
        }
        __syncthreads();
    }

    float* stage = smem + wid * 256;
    const int r  = lane >> 1;
    const int cq = (lane & 1) << 3;
#pragma unroll
    for (int i = 0; i < 4; i++) {
#pragma unroll
        for (int j = 0; j < 2; j++) {
            wmma::store_matrix_sync(stage, c[i][j], 16, wmma::mem_row_major);
            __syncwarp();
            const size_t row_g = (size_t)(m0 + wm * 64 + i * 16 + r);
            const size_t col_g = (size_t)(n0 + wn * 32 + j * 16 + cq);
            float4 v0 = *(float4*)&stage[r * 16 + cq];
            float4 v1 = *(float4*)&stage[r * 16 + cq + 4];
            float4 m0v = *(const float4*)&M[row_g * SEQ + col_g];
            float4 m1v = *(const float4*)&M[row_g * SEQ + col_g + 4];
            v0.x = v0.x * SCALE + m0v.x; v0.y = v0.y * SCALE + m0v.y;
            v0.z = v0.z * SCALE + m0v.z; v0.w = v0.w * SCALE + m0v.w;
            v1.x = v1.x * SCALE + m1v.x; v1.y = v1.y * SCALE + m1v.y;
            v1.z = v1.z * SCALE + m1v.z; v1.w = v1.w * SCALE + m1v.w;
            *(float4*)&C[row_g * SEQ + col_g] = v0;
            *(float4*)&C[row_g * SEQ + col_g + 4] = v1;
            __syncwarp();
        }
    }
}

// ============================================================
// PV: attn[b,s,h,:] = sum_t p[z,s,t] * v[b,t,kvh,:]   (NN GEMM)
// A = P [M=SEQ, K=SEQ] row-major; B = V [K, N=HD] row-major.
// ============================================================
__global__ void __launch_bounds__(256)
wattn_pv(const float* __restrict__ p, const float* __restrict__ v,
         float* __restrict__ out)
{
    const int z = blockIdx.z;
    const int b = z / NH, h = z % NH, kvh = h / GRP;
    const float* A = p + (size_t)z * SEQ * SEQ;
    const float* B = v + (size_t)b * SEQ * KVW + (size_t)kvh * HD;
    float* C = out + (size_t)b * SEQ * HIDN + (size_t)h * HD;

    __shared__ __align__(16) float smem[10240];
    float* sA[2] = { smem,        smem + 2560 };
    float* sB[2] = { smem + 5120, smem + 5120 + 2112 };

    const int tid  = threadIdx.x;
    const int wid  = tid >> 5;
    const int lane = tid & 31;
    const int m0 = blockIdx.y * BM;
    const int wm = wid & 1, wn = wid >> 1;

    wmma::fragment<wmma::accumulator, 16, 16, 8, float> c[4][2];
#pragma unroll
    for (int i = 0; i < 4; i++)
#pragma unroll
        for (int j = 0; j < 2; j++) wmma::fill_fragment(c[i][j], 0.f);

    const int lr  = tid >> 2;        // A rows 0..63
    const int lc4 = (tid & 3) << 2;
    const int brr = tid >> 5;        // B rows 0..7
    const int bcc = (tid & 31) << 2; // B cols 0..124
    const float* Abase = A + (size_t)(m0 + lr) * SEQ + lc4;

    float4 ra0, ra1, rb0, rb1;
    ra0 = *(const float4*)(Abase);
    ra1 = *(const float4*)(Abase + (size_t)64 * SEQ);
    rb0 = *(const float4*)(B + (size_t)brr * KVW + bcc);
    rb1 = *(const float4*)(B + (size_t)(brr + 8) * KVW + bcc);
    {
        float* a = sA[0] + lr * APITCH + lc4;
        a[0] = tf32r(ra0.x); a[1] = tf32r(ra0.y); a[2] = tf32r(ra0.z); a[3] = tf32r(ra0.w);
        float* a2 = sA[0] + (lr + 64) * APITCH + lc4;
        a2[0] = tf32r(ra1.x); a2[1] = tf32r(ra1.y); a2[2] = tf32r(ra1.z); a2[3] = tf32r(ra1.w);
        float* bp = sB[0] + brr * BPITCH_NN + bcc;
        bp[0] = tf32r(rb0.x); bp[1] = tf32r(rb0.y); bp[2] = tf32r(rb0.z); bp[3] = tf32r(rb0.w);
        float* b2 = sB[0] + (brr + 8) * BPITCH_NN + bcc;
        b2[0] = tf32r(rb1.x); b2[1] = tf32r(rb1.y); b2[2] = tf32r(rb1.z); b2[3] = tf32r(rb1.w);
    }
    __syncthreads();

    const int ntiles = SEQ / BKT;  // 64
    for (int t = 0; t < ntiles; t++) {
        const int cur = t & 1;
        if (t + 1 < ntiles) {
            const int k0 = (t + 1) * BKT;
            ra0 = *(const float4*)(Abase + k0);
            ra1 = *(const float4*)(Abase + (size_t)64 * SEQ + k0);
            rb0 = *(const float4*)(B + (size_t)(k0 + brr) * KVW + bcc);
            rb1 = *(const float4*)(B + (size_t)(k0 + brr + 8) * KVW + bcc);
        }
#pragma unroll
        for (int ks = 0; ks < BKT; ks += 8) {
            wmma::fragment<wmma::matrix_a, 16, 16, 8, wmma::precision::tf32, wmma::row_major> af[4];
            wmma::fragment<wmma::matrix_b, 16, 16, 8, wmma::precision::tf32, wmma::row_major> bf[2];
#pragma unroll
            for (int i = 0; i < 4; i++)
                wmma::load_matrix_sync(af[i], sA[cur] + (wm * 64 + i * 16) * APITCH + ks, APITCH);
#pragma unroll
            for (int j = 0; j < 2; j++)
                wmma::load_matrix_sync(bf[j], sB[cur] + ks * BPITCH_NN + (wn * 32 + j * 16), BPITCH_NN);
#pragma unroll
            for (int i = 0; i < 4; i++)
#pragma unroll
                for (int j = 0; j < 2; j++)
                    wmma::mma_sync(c[i][j], af[i], bf[j], c[i][j]);
        }
        if (t + 1 < ntiles) {
            const int nxt = cur ^ 1;
            float* a = sA[nxt] + lr * APITCH + lc4;
            a[0] = tf32r(ra0.x); a[1] = tf32r(ra0.y); a[2] = tf32r(ra0.z); a[3] = tf32r(ra0.w);
            float* a2 = sA[nxt] + (lr + 64) * APITCH + lc4;
            a2[0] = tf32r(ra1.x); a2[1] = tf32r(ra1.y); a2[2] = tf32r(ra1.z); a2[3] = tf32r(ra1.w);
            float* bp = sB[nxt] + brr * BPITCH_NN + bcc;
            bp[0] = tf32r(rb0.x); bp[1] = tf32r(rb0.y); bp[2] = tf32r(rb0.z); bp[3] = tf32r(rb0.w);
            float* b2 = sB[nxt] + (brr + 8) * BPITCH_NN + bcc;
            b2[0] = tf32r(rb1.x); b2[1] = tf32r(rb1.y); b2[2] = tf32r(rb1.z); b2[3] = tf32r(rb1.w);
        }
        __syncthreads();
    }

    float* stage = smem + wid * 256;
    const int r  = lane >> 1;
    const int cq = (lane & 1) << 3;
#pragma unroll
    for (int i = 0; i < 4; i++) {
#pragma unroll
        for (int j = 0; j < 2; j++) {
            wmma::store_matrix_sync(stage, c[i][j], 16, wmma::mem_row_major);
            __syncwarp();
            const size_t row_g = (size_t)(m0 + wm * 64 + i * 16 + r);
            const size_t col_g = (size_t)(wn * 32 + j * 16 + cq);
            float4 v0 = *(float4*)&stage[r * 16 + cq];
            float4 v1 = *(float4*)&stage[r * 16 + cq + 4];
            *(float4*)&C[row_g * HIDN + col_g] = v0;
            *(float4*)&C[row_g * HIDN + col_g + 4] = v1;
            __syncwarp();
        }
    }
}

// ---------------- elementwise / reduction kernels ----------------

__global__ void __launch_bounds__(256)
softmax_kernel(float* __restrict__ s)
{
    const size_t base = (size_t)blockIdx.x * SEQ;
    const int tid = threadIdx.x;
    __shared__ float red[8];

    float vals[4];
    float mx = -1e30f;
#pragma unroll
    for (int j = 0; j < 4; j++) {
        vals[j] = s[base + tid + j * 256];
        mx = fmaxf(mx, vals[j]);
    }
#pragma unroll
    for (int o = 16; o > 0; o >>= 1) mx = fmaxf(mx, __shfl_xor_sync(0xffffffffu, mx, o));
    if ((tid & 31) == 0) red[tid >> 5] = mx;
    __syncthreads();
    float m2 = fmaxf(fmaxf(fmaxf(red[0], red[1]), fmaxf(red[2], red[3])),
                     fmaxf(fmaxf(red[4], red[5]), fmaxf(red[6], red[7])));
    __syncthreads();

    float sum = 0.f;
#pragma unroll
    for (int j = 0; j < 4; j++) {
        vals[j] = expf(vals[j] - m2);
        sum += vals[j];
    }
#pragma unroll
    for (int o = 16; o > 0; o >>= 1) sum += __shfl_xor_sync(0xffffffffu, sum, o);
    if ((tid & 31) == 0) red[tid >> 5] = sum;
    __syncthreads();
    float tot = red[0] + red[1] + red[2] + red[3] + red[4] + red[5] + red[6] + red[7];
    float inv = 1.f / tot;
#pragma unroll
    for (int j = 0; j < 4; j++) s[base + tid + j * 256] = vals[j] * inv;
}

__global__ void __launch_bounds__(256)
rmsnorm_kernel(const float* __restrict__ x, const float* __restrict__ w,
               float* __restrict__ out)
{
    const size_t base = (size_t)blockIdx.x * HIDN;
    const int tid = threadIdx.x;
    __shared__ float red[8];

    float v[8];
    float ss = 0.f;
#pragma unroll
    for (int j = 0; j < 8; j++) {
        v[j] = x[base + tid + j * 256];
        ss += v[j] * v[j];
    }
#pragma unroll
    for (int o = 16; o > 0; o >>= 1) ss += __shfl_xor_sync(0xffffffffu, ss, o);
    if ((tid & 31) == 0) red[tid >> 5] = ss;
    __syncthreads();
    float tot = red[0] + red[1] + red[2] + red[3] + red[4] + red[5] + red[6] + red[7];
    float r = rsqrtf(tot * (1.f / HIDN) + EPSV);
#pragma unroll
    for (int j = 0; j < 8; j++)
        out[base + tid + j * 256] = v[j] * r * w[tid + j * 256];
}

__global__ void __launch_bounds__(128)
head_rms_rope_kernel(float* __restrict__ buf, const float* __restrict__ w,
                     const float* __restrict__ cs, const float* __restrict__ sn,
                     int nheads)
{
    const int t = blockIdx.x;
    const int h = blockIdx.y;
    const int i = threadIdx.x;
    const size_t idx = (size_t)t * nheads * HD + (size_t)h * HD + i;

    float v = buf[idx];
    float ss = v * v;
#pragma unroll
    for (int o = 16; o > 0; o >>= 1) ss += __shfl_xor_sync(0xffffffffu, ss, o);
    __shared__ float red[4];
    if ((i & 31) == 0) red[i >> 5] = ss;
    __syncthreads();
    float tot = red[0] + red[1] + red[2] + red[3];
    float n = v * rsqrtf(tot * (1.f / HD) + EPSV) * w[i];

    __shared__ float sm[HD];
    sm[i] = n;
    __syncthreads();
    float rot = (i < 64) ? -sm[i + 64] : sm[i - 64];
    buf[idx] = n * cs[(size_t)t * HD + i] + rot * sn[(size_t)t * HD + i];
}

__global__ void __launch_bounds__(256)
silu_mul_kernel(float* __restrict__ g, const float* __restrict__ u, size_t n)
{
    size_t i = (size_t)blockIdx.x * blockDim.x + threadIdx.x;
    size_t stride = (size_t)gridDim.x * blockDim.x;
    for (; i < n; i += stride) {
        float gv = g[i];
        g[i] = gv / (1.f + expf(-gv)) * u[i];
    }
}

extern "C" void kernel_launch(void* const* d_in, const int* in_sizes, int n_in,
                              void* d_out, int out_size)
{
    const float* x    = (const float*)d_in[0];
    const float* cosv = (const float*)d_in[1];
    const float* sinv = (const float*)d_in[2];
    const float* mask = (const float*)d_in[3];
    const float* wq   = (const float*)d_in[4];
    const float* bq   = (const float*)d_in[5];
    const float* wk   = (const float*)d_in[6];
    const float* bk   = (const float*)d_in[7];
    const float* wv   = (const float*)d_in[8];
    const float* bv   = (const float*)d_in[9];
    const float* wo   = (const float*)d_in[10];
    const float* qw   = (const float*)d_in[11];
    const float* kw   = (const float*)d_in[12];
    const float* ln1  = (const float*)d_in[13];
    const float* ln2  = (const float*)d_in[14];
    const float* wg   = (const float*)d_in[15];
    const float* wu   = (const float*)d_in[16];
    const float* wd   = (const float*)d_in[17];
    float* out = (float*)d_out;

    float* s = nullptr;
    cudaGetSymbolAddress((void**)&s, g_scratch);
    float* h      = s + OFF_H;
    float* q      = s + OFF_Q;
    float* kbuf   = s + OFF_K;
    float* vbuf   = s + OFF_V;
    float* scores = s + OFF_SCORES;
    float* attn   = s + OFF_ATTN;
    float* x2     = s + OFF_X2;
    float* gate   = s + OFF_GATE;
    float* up     = s + OFF_UP;

    // 1. h = rmsnorm(x, ln1)
    rmsnorm_kernel<<<T_TOK, 256>>>(x, ln1, h);

    // 2-4. QKV projections (+bias)
    wgemm_tn<1><<<dim3(HIDN / BN, T_TOK / BM), 256>>>(h, HIDN, wq, HIDN, q, HIDN, HIDN, bq, nullptr);
    wgemm_tn<1><<<dim3(KVW  / BN, T_TOK / BM), 256>>>(h, HIDN, wk, HIDN, kbuf, KVW, HIDN, bk, nullptr);
    wgemm_tn<1><<<dim3(KVW  / BN, T_TOK / BM), 256>>>(h, HIDN, wv, HIDN, vbuf, KVW, HIDN, bv, nullptr);

    // 5-6. per-head RMS + RoPE (in place)
    head_rms_rope_kernel<<<dim3(T_TOK, NH),  HD>>>(q,    qw, cosv, sinv, NH);
    head_rms_rope_kernel<<<dim3(T_TOK, NKV), HD>>>(kbuf, kw, cosv, sinv, NKV);

    // 7. scores = QK^T * scale + mask
    wattn_scores<<<dim3(SEQ / BN, SEQ / BM, BATCH * NH), 256>>>(q, kbuf, mask, scores);

    // 8. softmax over keys
    softmax_kernel<<<BATCH * NH * SEQ, 256>>>(scores);

    // 9. attn = P @ V
    wattn_pv<<<dim3(1, SEQ / BM, BATCH * NH), 256>>>(scores, vbuf, attn);

    // 10. x2 = x + attn @ wo^T
    wgemm_tn<2><<<dim3(HIDN / BN, T_TOK / BM), 256>>>(attn, HIDN, wo, HIDN, x2, HIDN, HIDN, nullptr, x);

    // 11. h = rmsnorm(x2, ln2)
    rmsnorm_kernel<<<T_TOK, 256>>>(x2, ln2, h);

    // 12-13. gate / up projections
    wgemm_tn<0><<<dim3(FF / BN, T_TOK / BM), 256>>>(h, HIDN, wg, HIDN, gate, FF, HIDN, nullptr, nullptr);
    wgemm_tn<0><<<dim3(FF / BN, T_TOK / BM), 256>>>(h, HIDN, wu, HIDN, up, FF, HIDN, nullptr, nullptr);

    // 14. gate = silu(gate) * up
    silu_mul_kernel<<<8192, 256>>>(gate, up, (size_t)T_TOK * FF);

    // 15. out = x2 + gate @ wd^T
    wgemm_tn<2><<<dim3(HIDN / BN, T_TOK / BM), 256>>>(gate, FF, wd, FF, out, HIDN, FF, nullptr, x2);
}